// round 11
// baseline (speedup 1.0000x reference)
#include <cuda_runtime.h>
#include <cuda_fp16.h>
#include <cstdint>
#include <cstddef>

#define FMAXD 1024
#define GMAX  256
#define GWMAX 64
#define MAXN  40960

// ---------------- scratch (static device globals; no runtime allocation) ---
__device__ __half g_feath[(size_t)MAXN * FMAXD];            // feat in fp16 (GEMM A)
__device__ __half g_sW[(size_t)GWMAX * FMAXD * FMAXD];      // per-graph scaled W (B)
__device__ float  g_biasg[GWMAX * FMAXD];                   // per-graph bias (t-term + b)
__device__ float  g_sum[GMAX * FMAXD];
__device__ float  g_sq[GMAX * FMAXD];
__device__ float  g_s[GMAX * FMAXD];
__device__ float  g_t[GMAX * FMAXD];
__device__ int    g_cnt[GMAX];

// ---------------- helpers ---------------------------------------------------
__device__ __forceinline__ void cp16(uint32_t dst, const void* src) {
    asm volatile("cp.async.cg.shared.global [%0], [%1], 16;\n" :: "r"(dst), "l"(src));
}
__device__ __forceinline__ void cp_commit() { asm volatile("cp.async.commit_group;\n"); }
template <int n> __device__ __forceinline__ void cp_wait() {
    asm volatile("cp.async.wait_group %0;\n" :: "n"(n));
}
__device__ __forceinline__ void l2_prefetch(const void* p) {
    asm volatile("prefetch.global.L2 [%0];" :: "l"(p));
}

// ---------------- small kernels ---------------------------------------------
__global__ void zero_stats() {
    int i = blockIdx.x * blockDim.x + threadIdx.x;
    if (i < GMAX * FMAXD) { g_sum[i] = 0.f; g_sq[i] = 0.f; }
    if (i < GMAX) g_cnt[i] = 0;
}

__global__ void count_nodes(const int* __restrict__ seg, int N) {
    __shared__ int h[GMAX];
    for (int i = threadIdx.x; i < GMAX; i += blockDim.x) h[i] = 0;
    __syncthreads();
    int i = blockIdx.x * blockDim.x + threadIdx.x;
    if (i < N) atomicAdd(&h[seg[i]], 1);
    __syncthreads();
    for (int i = threadIdx.x; i < GMAX; i += blockDim.x)
        if (h[i]) atomicAdd(&g_cnt[i], h[i]);
}

// Pass 1: feat = ||fv+1e-8|| (f32 math), per-graph sum/sumsq in f32,
// feat stored as fp16 (GEMM A operand).
__global__ void pass1(const float* __restrict__ fv, const int* __restrict__ seg,
                      int N, int F, int npb) {
    int q  = blockIdx.x * blockDim.x + threadIdx.x;   // feature quad
    if (q >= F / 4) return;
    int n0 = blockIdx.y * npb;
    if (n0 >= N) return;
    int nend = min(n0 + npb, N);
    float s1[4] = {0.f, 0.f, 0.f, 0.f};
    float s2[4] = {0.f, 0.f, 0.f, 0.f};
    int curg = seg[n0];
    int f0 = 4 * q;
    for (int n = n0; n < nend; ++n) {
        int g = seg[n];
        if (g != curg) {
#pragma unroll
            for (int k = 0; k < 4; ++k) {
                atomicAdd(&g_sum[curg * F + f0 + k], s1[k]);
                atomicAdd(&g_sq[curg * F + f0 + k], s2[k]);
                s1[k] = 0.f; s2[k] = 0.f;
            }
            curg = g;
        }
        const float4* p = reinterpret_cast<const float4*>(fv + ((size_t)n * F + f0) * 3);
        float4 a = p[0], b = p[1], c = p[2];
        float x0 = a.x + 1e-8f, y0 = a.y + 1e-8f, z0 = a.z + 1e-8f;
        float x1 = a.w + 1e-8f, y1 = b.x + 1e-8f, z1 = b.y + 1e-8f;
        float x2 = b.z + 1e-8f, y2 = b.w + 1e-8f, z2 = c.x + 1e-8f;
        float x3 = c.y + 1e-8f, y3 = c.z + 1e-8f, z3 = c.w + 1e-8f;
        float4 ft;
        ft.x = sqrtf(fmaf(x0, x0, fmaf(y0, y0, z0 * z0)));
        ft.y = sqrtf(fmaf(x1, x1, fmaf(y1, y1, z1 * z1)));
        ft.z = sqrtf(fmaf(x2, x2, fmaf(y2, y2, z2 * z2)));
        ft.w = sqrtf(fmaf(x3, x3, fmaf(y3, y3, z3 * z3)));
        __half2 h01, h23;
        h01.x = __float2half(ft.x); h01.y = __float2half(ft.y);
        h23.x = __float2half(ft.z); h23.y = __float2half(ft.w);
        __half2* dst = reinterpret_cast<__half2*>(g_feath + (size_t)n * F + f0);
        dst[0] = h01; dst[1] = h23;
        s1[0] += ft.x; s2[0] = fmaf(ft.x, ft.x, s2[0]);
        s1[1] += ft.y; s2[1] = fmaf(ft.y, ft.y, s2[1]);
        s1[2] += ft.z; s2[2] = fmaf(ft.z, ft.z, s2[2]);
        s1[3] += ft.w; s2[3] = fmaf(ft.w, ft.w, s2[3]);
    }
#pragma unroll
    for (int k = 0; k < 4; ++k) {
        atomicAdd(&g_sum[curg * F + f0 + k], s1[k]);
        atomicAdd(&g_sq[curg * F + f0 + k], s2[k]);
    }
}

// Per-(g,f) affine coefficients: y = feat*s + t
__global__ void stats(const float* __restrict__ alpha, const float* __restrict__ beta,
                      const float* __restrict__ gamma, int F) {
    int f = blockIdx.x * blockDim.x + threadIdx.x;
    int g = blockIdx.y;
    int c = g_cnt[g];
    if (c == 0) return;
    float invc = 1.f / (float)c;
    size_t idx = (size_t)g * F + f;
    float u  = g_sum[idx] * invc;
    float u2 = alpha[f] * u;
    float m2 = g_sq[idx] * invc;
    float sigma = m2 - 2.f * u2 * u + u2 * u2;
    float sn = sqrtf(sigma + 1e-6f);
    float iv = 1.f / (sn + 1e-6f);
    float sv = gamma[f] * iv;
    g_s[idx] = sv;
    g_t[idx] = fmaf(-u2, sv, beta[f]);
}

// sW[g][j][f] = half(s[g][f] * W[j][f])  — per-graph scaled weights
__global__ void scaled_w(const float* __restrict__ W, const int* __restrict__ numg, int F) {
    int g = blockIdx.y;
    if (g >= *numg || g >= GWMAX) return;
    int i = blockIdx.x * blockDim.x + threadIdx.x;   // 8-elem chunk of F*F
    if (i >= F * F / 8) return;
    int row = i / (F / 8), c8 = i % (F / 8);
    const float4* wp = reinterpret_cast<const float4*>(W + (size_t)row * F + c8 * 8);
    const float4* sp = reinterpret_cast<const float4*>(g_s + (size_t)g * F + c8 * 8);
    float4 w0 = wp[0], w1 = wp[1], s0 = sp[0], s1 = sp[1];
    __half2 o[4];
    o[0].x = __float2half(w0.x * s0.x); o[0].y = __float2half(w0.y * s0.y);
    o[1].x = __float2half(w0.z * s0.z); o[1].y = __float2half(w0.w * s0.w);
    o[2].x = __float2half(w1.x * s1.x); o[2].y = __float2half(w1.y * s1.y);
    o[3].x = __float2half(w1.z * s1.z); o[3].y = __float2half(w1.w * s1.w);
    __half* dst = g_sW + (size_t)g * F * F + (size_t)row * F + c8 * 8;
    *reinterpret_cast<uint4*>(dst) = *reinterpret_cast<const uint4*>(o);
}

// biasg[g][j] = b[j] + sum_f t[g][f] * W[j][f]   (exact f32 t-term)
__global__ void bias_g(const float* __restrict__ W, const float* __restrict__ b,
                       const int* __restrict__ numg, int F) {
    int g = blockIdx.y;
    if (g >= *numg || g >= GWMAX) return;
    int j = blockIdx.x * blockDim.x + threadIdx.x;
    __shared__ float ts[FMAXD];
    for (int f = threadIdx.x; f < F; f += blockDim.x) ts[f] = g_t[(size_t)g * F + f];
    __syncthreads();
    if (j >= F) return;
    float acc = b[j];
    const float4* wr = reinterpret_cast<const float4*>(W + (size_t)j * F);
    for (int f4 = 0; f4 < F / 4; ++f4) {
        float4 w = wr[f4];
        const float* t4 = ts + 4 * f4;
        acc = fmaf(t4[0], w.x, acc);
        acc = fmaf(t4[1], w.y, acc);
        acc = fmaf(t4[2], w.z, acc);
        acc = fmaf(t4[3], w.w, acc);
    }
    g_biasg[g * F + j] = acc;
}

// ---------------- fp16 mma.sync GEMM with fused final rescale epilogue ------
// A = raw feat (fp16), B = per-graph scaled W. Tiles are taken WITHIN a graph
// (self-tiled from device-side G). BM=256, BN=128, 512 thr, 4-stage pipeline.
#define BM 256
#define BN 128
#define BK 64
#define RSTR 72                          // 64 data + 8 pad halfs (144B rows)
#define A_STG (BM * RSTR)
#define B_STG (BN * RSTR)
#define NSTAGE 4
#define SMEM_B ((NSTAGE * (A_STG + B_STG)) * 2)   // 221184 bytes
#define NTHR 512
#define YMAX 256

__global__ void __launch_bounds__(NTHR, 1) gemm_fused(
    const float* __restrict__ fv, const float* __restrict__ zeta,
    const int* __restrict__ numg, float* __restrict__ out, int N, int F) {
    int G = *numg;
    int NPG = N / G;
    int tpg = (NPG + BM - 1) / BM;
    if ((int)blockIdx.y >= G * tpg) return;
    int g = blockIdx.y / tpg, mt = blockIdx.y % tpg;
    int mbase = g * NPG;                 // first node of this graph
    int t0 = mt * BM;                    // local tile row base within graph

    extern __shared__ __half sm[];
    __half* As = sm;
    __half* Bs = sm + NSTAGE * A_STG;
    int tid = threadIdx.x;
    int n0 = blockIdx.x * BN;
    uint32_t asBase = (uint32_t)__cvta_generic_to_shared(As);
    uint32_t bsBase = (uint32_t)__cvta_generic_to_shared(Bs);
    int NK = F / BK;                     // 16
    const __half* Bsrc = g_sW + (size_t)g * F * F;

    float acc[4][4][4];
#pragma unroll
    for (int a = 0; a < 4; ++a)
#pragma unroll
        for (int b = 0; b < 4; ++b)
#pragma unroll
            for (int c2 = 0; c2 < 4; ++c2) acc[a][b][c2] = 0.f;

    int wid = tid / 32, lane = tid % 32;
    int warpM = (wid >> 2) * 64;
    int warpN = (wid & 3) * 32;
    int r = lane >> 2, c = lane & 3;

    auto loadAB = [&](int st, int kt) {
#pragma unroll
        for (int it = 0; it < 4; ++it) {    // A: 2048 chunks
            int id = tid + NTHR * it;
            int row = id >> 3, ch = id & 7;
            int grl = t0 + row; if (grl > NPG - 1) grl = NPG - 1;
            const void* srcA = g_feath + (size_t)(mbase + grl) * F + kt * BK + ch * 8;
            cp16(asBase + (uint32_t)(st * A_STG + row * RSTR) * 2u + ch * 16u, srcA);
        }
#pragma unroll
        for (int it = 0; it < 2; ++it) {    // B: 1024 chunks
            int id = tid + NTHR * it;
            int row = id >> 3, ch = id & 7;
            const void* srcB = Bsrc + (size_t)(n0 + row) * F + kt * BK + ch * 8;
            cp16(bsBase + (uint32_t)(st * B_STG + row * RSTR) * 2u + ch * 16u, srcB);
        }
    };

    loadAB(0, 0); cp_commit();
    loadAB(1, 1); cp_commit();
    loadAB(2, 2); cp_commit();

    int l8 = lane & 7, lg = lane >> 3;

    for (int kt = 0; kt < NK; ++kt) {
        int st = kt & 3;
        cp_wait<2>();
        __syncthreads();
        {
            int kn = kt + NSTAGE - 1;
            if (kn < NK) loadAB(kn & 3, kn);
            cp_commit();
        }
        if (kt == 4) {
            // L2-prefetch epilogue fv footprint (256 rows x 128 feats x 12B)
#pragma unroll
            for (int i = 0; i < 6; ++i) {
                int id = tid + NTHR * i;
                int row = id / 12, sl = id % 12;
                int grl = t0 + row; if (grl > NPG - 1) grl = NPG - 1;
                const char* p = reinterpret_cast<const char*>(
                    fv + ((size_t)(mbase + grl) * F + n0) * 3) + sl * 128;
                l2_prefetch(p);
            }
        }
        const __half* At = As + st * A_STG;
        const __half* Bt = Bs + st * B_STG;
#pragma unroll
        for (int ks = 0; ks < 4; ++ks) {
            uint32_t a[4][4], bb[4][2];
#pragma unroll
            for (int mtq = 0; mtq < 4; ++mtq) {
                int arow = warpM + mtq * 16 + ((lg & 1) ? 8 : 0) + l8;
                int acol = ks * 16 + ((lg >> 1) ? 8 : 0);
                uint32_t addr = (uint32_t)__cvta_generic_to_shared(At + arow * RSTR + acol);
                asm volatile("ldmatrix.sync.aligned.m8n8.x4.shared.b16 {%0,%1,%2,%3}, [%4];"
                             : "=r"(a[mtq][0]), "=r"(a[mtq][1]), "=r"(a[mtq][2]), "=r"(a[mtq][3])
                             : "r"(addr));
            }
#pragma unroll
            for (int pp = 0; pp < 2; ++pp) {
                int brow = warpN + pp * 16 + ((lg >> 1) ? 8 : 0) + l8;
                int bcol = ks * 16 + ((lg & 1) ? 8 : 0);
                uint32_t addr = (uint32_t)__cvta_generic_to_shared(Bt + brow * RSTR + bcol);
                uint32_t r0, r1, r2, r3;
                asm volatile("ldmatrix.sync.aligned.m8n8.x4.shared.b16 {%0,%1,%2,%3}, [%4];"
                             : "=r"(r0), "=r"(r1), "=r"(r2), "=r"(r3) : "r"(addr));
                bb[pp * 2 + 0][0] = r0; bb[pp * 2 + 0][1] = r1;
                bb[pp * 2 + 1][0] = r2; bb[pp * 2 + 1][1] = r3;
            }
#pragma unroll
            for (int mtq = 0; mtq < 4; ++mtq)
#pragma unroll
                for (int nt = 0; nt < 4; ++nt)
                    asm volatile(
                        "mma.sync.aligned.m16n8k16.row.col.f32.f16.f16.f32 "
                        "{%0,%1,%2,%3},{%4,%5,%6,%7},{%8,%9},{%0,%1,%2,%3};\n"
                        : "+f"(acc[mtq][nt][0]), "+f"(acc[mtq][nt][1]),
                          "+f"(acc[mtq][nt][2]), "+f"(acc[mtq][nt][3])
                        : "r"(a[mtq][0]), "r"(a[mtq][1]), "r"(a[mtq][2]), "r"(a[mtq][3]),
                          "r"(bb[nt][0]), "r"(bb[nt][1]));
        }
    }
    cp_wait<0>();

    // Fused epilogue: gate = acc + biasg[g][j];
    // out[n,j,:] = gate * fv[n,j,:] / (feat + zeta[j] + 1e-8), feat recomputed.
    const float* bg = g_biasg + (size_t)g * F;
#pragma unroll
    for (int mtq = 0; mtq < 4; ++mtq) {
#pragma unroll
        for (int half = 0; half < 2; ++half) {
            int lrow = t0 + warpM + mtq * 16 + r + half * 8;
            if (lrow >= NPG) continue;
            int n = mbase + lrow;
#pragma unroll
            for (int nt = 0; nt < 4; ++nt) {
                int j = n0 + warpN + nt * 8 + 2 * c;
                float d0 = acc[mtq][nt][half * 2 + 0];
                float d1 = acc[mtq][nt][half * 2 + 1];
                size_t base = ((size_t)n * F + j) * 3;
                const float2* vp = reinterpret_cast<const float2*>(fv + base);
                float2 v0 = vp[0], v1 = vp[1], v2 = vp[2];
                float xa = v0.x + 1e-8f, ya = v0.y + 1e-8f, za = v1.x + 1e-8f;
                float xb = v1.y + 1e-8f, yb = v2.x + 1e-8f, zb = v2.y + 1e-8f;
                float ft0 = sqrtf(fmaf(xa, xa, fmaf(ya, ya, za * za)));
                float ft1 = sqrtf(fmaf(xb, xb, fmaf(yb, yb, zb * zb)));
                float gt0 = d0 + bg[j];
                float gt1 = d1 + bg[j + 1];
                float s0 = gt0 / (ft0 + zeta[j] + 1e-8f);
                float s1 = gt1 / (ft1 + zeta[j + 1] + 1e-8f);
                float2* op = reinterpret_cast<float2*>(out + base);
                float2 o0, o1, o2;
                o0.x = s0 * v0.x; o0.y = s0 * v0.y;
                o1.x = s0 * v1.x; o1.y = s1 * v1.y;
                o2.x = s1 * v2.x; o2.y = s1 * v2.y;
                op[0] = o0; op[1] = o1; op[2] = o2;
            }
        }
    }
}

// ---------------- launch -----------------------------------------------------
extern "C" void kernel_launch(void* const* d_in, const int* in_sizes, int n_in,
                              void* d_out, int out_size) {
    int o = (n_in >= 9) ? 3 : 2;
    const float* fv    = (const float*)d_in[0];
    const int*   seg   = (const int*)d_in[1];
    const int*   numg  = (const int*)d_in[2];
    const float* alpha = (const float*)d_in[o];
    const float* beta  = (const float*)d_in[o + 1];
    const float* gamma = (const float*)d_in[o + 2];
    const float* zeta  = (const float*)d_in[o + 3];
    const float* W     = (const float*)d_in[o + 4];
    const float* bias  = (const float*)d_in[o + 5];
    int F = in_sizes[o];
    int N = in_sizes[0] / (3 * F);
    float* out = (float*)d_out;

    zero_stats<<<(GMAX * FMAXD + 255) / 256, 256>>>();
    count_nodes<<<(N + 255) / 256, 256>>>(seg, N);

    int npb = 25;
    dim3 g1((F / 4 + 255) / 256, (N + npb - 1) / npb);
    pass1<<<g1, 256>>>(fv, seg, N, F, npb);

    dim3 g2(F / 256, GMAX);
    stats<<<g2, 256>>>(alpha, beta, gamma, F);

    dim3 g3((F * F / 8 + 255) / 256, GWMAX);
    scaled_w<<<g3, 256>>>(W, numg, F);

    dim3 g4(F / 256, GWMAX);
    bias_g<<<g4, 256>>>(W, bias, numg, F);

    cudaFuncSetAttribute(gemm_fused, cudaFuncAttributeMaxDynamicSharedMemorySize, SMEM_B);
    dim3 gg(F / BN, YMAX);
    gemm_fused<<<gg, NTHR, SMEM_B>>>(fv, zeta, numg, out, N, F);
}